// round 14
// baseline (speedup 1.0000x reference)
#include <cuda_runtime.h>

#define BINS     64
#define NB       (BINS * BINS)
#define BATCH    2
#define NELEM    (192 * 224 * 192)   /* 8,257,536 per batch */
#define N4       (NELEM / 4)
#define NHALF    (N4 / 2)
#define EPSF     1e-10f

#define NBLOCKS  296                 /* 2/SM x 148 SM: exactly one wave */
#define HTHREADS 512
#define BPB      (NBLOCKS / 2)       /* blocks per batch = 148 */

// Scratch. Self-restoring: everything reset by the combine block.
__device__ unsigned int g_hist[BATCH * NB];   // static-zeroed
__device__ unsigned int g_minmax[8] = {       // [c*2]=min-enc, [c*2+1]=max-enc
    0xFFFFFFFFu, 0u, 0xFFFFFFFFu, 0u,         // combo = arr*2 + b (arr0=fixed)
    0xFFFFFFFFu, 0u, 0xFFFFFFFFu, 0u
};
__device__ unsigned int g_barB[2]  = {0, 0};  // per-batch phase barrier
__device__ unsigned int g_doneB[2] = {0, 0};  // per-batch flush counter
__device__ unsigned int g_done2    = 0;       // combiner election
__device__ float        g_nmi[2]   = {0.f, 0.f};

__device__ __forceinline__ unsigned int fenc(float f) {
    unsigned int u = __float_as_uint(f);
    return (u & 0x80000000u) ? ~u : (u | 0x80000000u);
}
__device__ __forceinline__ float fdec(unsigned int e) {
    unsigned int u = (e & 0x80000000u) ? (e & 0x7fffffffu) : ~e;
    return __uint_as_float(u);
}
__device__ __forceinline__ int binof(float x, float s, float c) {
    return min(max(__float2int_rz(fmaf(x, s, c)), 0), BINS - 1);
}

// R13 structure (static partition, per-batch barriers, split per-batch
// finals). Single change: 296 blocks (2/SM, 32 warps/SM) instead of 444 —
// above the ATOMS saturation knee (R4: hist time flat from 23 warps/SM;
// R12's regression was at 16 warps/SM), and flush REDG drops 33%.
__global__ void __launch_bounds__(HTHREADS, 3)
fusedK(const float* __restrict__ fixedp,
       const float* __restrict__ warpedp,
       const float* __restrict__ pred,
       const float* __restrict__ tru,
       float* __restrict__ out) {
    __shared__ unsigned int sh[NB];
    __shared__ float red[16];
    __shared__ float hmarg[2];
    __shared__ unsigned int s_last;
    int t   = threadIdx.x;
    int w   = t >> 5, l = t & 31;
    int bid = blockIdx.x;
    int b    = (bid >= BPB) ? 1 : 0;     // batch owned by this block
    int xbid = bid - b * BPB;            // 0..147 within batch

    // Zero private histogram early (hidden under phase-1 streaming).
    for (int i = t; i < NB; i += HTHREADS) sh[i] = 0u;

    const float4* f4 = (const float4*)(fixedp  + (size_t)b * NELEM);
    const float4* w4 = (const float4*)(warpedp + (size_t)b * NELEM);

    // ---- Phase 1: REVERSE min/max (tail L2-resident from previous
    // replay's forward phase 2; finishes at heads, feeding phase 2). ----
    {
        float fmn = 3.4e38f, fmx = -3.4e38f, wmn = 3.4e38f, wmx = -3.4e38f;
        for (int i = xbid * HTHREADS + t; i < N4; i += BPB * HTHREADS) {
            int j = (N4 - 1) - i;
            float4 f = f4[j];
            float4 wv = w4[j];
            fmn = fminf(fmn, fminf(fminf(f.x, f.y), fminf(f.z, f.w)));
            fmx = fmaxf(fmx, fmaxf(fmaxf(f.x, f.y), fmaxf(f.z, f.w)));
            wmn = fminf(wmn, fminf(fminf(wv.x, wv.y), fminf(wv.z, wv.w)));
            wmx = fmaxf(wmx, fmaxf(fmaxf(wv.x, wv.y), fmaxf(wv.z, wv.w)));
        }
        #pragma unroll
        for (int o = 16; o; o >>= 1) {
            fmn = fminf(fmn, __shfl_down_sync(0xFFFFFFFFu, fmn, o));
            fmx = fmaxf(fmx, __shfl_down_sync(0xFFFFFFFFu, fmx, o));
            wmn = fminf(wmn, __shfl_down_sync(0xFFFFFFFFu, wmn, o));
            wmx = fmaxf(wmx, __shfl_down_sync(0xFFFFFFFFu, wmx, o));
        }
        __shared__ float s0[16], s1[16], s2[16], s3[16];
        if (l == 0) { s0[w] = fmn; s1[w] = fmx; s2[w] = wmn; s3[w] = wmx; }
        __syncthreads();
        if (t == 0) {
            float a = s0[0], bb = s1[0], c = s2[0], d = s3[0];
            #pragma unroll
            for (int k = 1; k < 16; k++) {
                a = fminf(a, s0[k]); bb = fmaxf(bb, s1[k]);
                c = fminf(c, s2[k]); d = fmaxf(d, s3[k]);
            }
            atomicMin(&g_minmax[(0 * 2 + b) * 2 + 0], fenc(a));
            atomicMax(&g_minmax[(0 * 2 + b) * 2 + 1], fenc(bb));
            atomicMin(&g_minmax[(1 * 2 + b) * 2 + 0], fenc(c));
            atomicMax(&g_minmax[(1 * 2 + b) * 2 + 1], fenc(d));
            __threadfence();
            atomicAdd(&g_barB[b], 1u);
        }
    }

    // ---- Per-batch barrier: wait only for this batch's 148 blocks. ----
    if (t == 0) {
        while (atomicAdd(&g_barB[b], 0u) < BPB) __nanosleep(64);
    }
    __syncthreads();
    __threadfence();   // acquire: order g_minmax reads after the spin

    // ---- Phase 2: FORWARD histogram, two-stream for MLP. ----
    float fmn = fdec(g_minmax[(0 * 2 + b) * 2 + 0]);
    float fmx = fdec(g_minmax[(0 * 2 + b) * 2 + 1]);
    float wmn = fdec(g_minmax[(1 * 2 + b) * 2 + 0]);
    float wmx = fdec(g_minmax[(1 * 2 + b) * 2 + 1]);
    float fs = (float)(BINS - 1) / (fmx - fmn + EPSF);
    float ws = (float)(BINS - 1) / (wmx - wmn + EPSF);
    float fc = -fmn * fs;
    float wc = -wmn * ws;

    for (int i = xbid * HTHREADS + t; i < NHALF; i += BPB * HTHREADS) {
        float4 f0 = f4[i];
        float4 w0 = w4[i];
        float4 f1 = f4[i + NHALF];
        float4 w1 = w4[i + NHALF];
        atomicAdd(&sh[binof(f0.x, fs, fc) * BINS + binof(w0.x, ws, wc)], 1u);
        atomicAdd(&sh[binof(f0.y, fs, fc) * BINS + binof(w0.y, ws, wc)], 1u);
        atomicAdd(&sh[binof(f0.z, fs, fc) * BINS + binof(w0.z, ws, wc)], 1u);
        atomicAdd(&sh[binof(f0.w, fs, fc) * BINS + binof(w0.w, ws, wc)], 1u);
        atomicAdd(&sh[binof(f1.x, fs, fc) * BINS + binof(w1.x, ws, wc)], 1u);
        atomicAdd(&sh[binof(f1.y, fs, fc) * BINS + binof(w1.y, ws, wc)], 1u);
        atomicAdd(&sh[binof(f1.z, fs, fc) * BINS + binof(w1.z, ws, wc)], 1u);
        atomicAdd(&sh[binof(f1.w, fs, fc) * BINS + binof(w1.w, ws, wc)], 1u);
    }
    __syncthreads();

    // Flush as packed u64 (low half can't carry into high: counts << 2^32).
    unsigned long long* gh64 = (unsigned long long*)(g_hist + b * NB);
    const unsigned long long* sh64 = (const unsigned long long*)sh;
    for (int i = t; i < NB / 2; i += HTHREADS) {
        unsigned long long v = sh64[i];
        if (v) atomicAdd(&gh64[i], v);
    }
    __threadfence();
    __syncthreads();

    // ---- Per-batch last-block does this batch's entropy/NMI. ----
    if (t == 0) {
        unsigned int old = atomicAdd(&g_doneB[b], 1u);
        s_last = (old == BPB - 1) ? 1u : 0u;
    }
    __syncthreads();
    if (!s_last) return;

    __threadfence();
    float* shf = (float*)sh;
    const float invN = 1.0f / ((float)NELEM + EPSF);
    {
        unsigned int* gh = g_hist + b * NB;
        if (t < 2) hmarg[t] = 0.f;

        float hj = 0.f;
        #pragma unroll
        for (int k = 0; k < NB / HTHREADS; k++) {
            int i = t + k * HTHREADS;
            float c = (float)__ldcg(&gh[i]);
            gh[i] = 0u;              // self-restore
            shf[i] = c;
            float p = c * invN;
            hj -= p * __logf(p + EPSF);
        }
        #pragma unroll
        for (int o = 16; o; o >>= 1) hj += __shfl_down_sync(0xFFFFFFFFu, hj, o);
        if (l == 0) red[w] = hj;
        __syncthreads();

        float hterm = 0.f;
        if (t < 64) {
            float rs = 0.f;
            #pragma unroll
            for (int j = 0; j < BINS; j++) rs += shf[t * BINS + ((j + t) & 63)];
            float p = rs * invN;
            hterm = -p * __logf(p + EPSF);
        } else if (t < 128) {
            int c = t - 64;
            float cs = 0.f;
            #pragma unroll
            for (int j = 0; j < BINS; j++) cs += shf[j * BINS + c];
            float p = cs * invN;
            hterm = -p * __logf(p + EPSF);
        }
        #pragma unroll
        for (int o = 16; o; o >>= 1)
            hterm += __shfl_down_sync(0xFFFFFFFFu, hterm, o);
        if (l == 0 && w < 4) atomicAdd(&hmarg[w >> 1], hterm);
        __syncthreads();

        if (t == 0) {
            float h_j = 0.f;
            #pragma unroll
            for (int k = 0; k < 16; k++) h_j += red[k];
            float h_f = hmarg[0], h_w = hmarg[1];
            g_nmi[b] = 2.f * (h_f + h_w - h_j) / (h_f + h_w + EPSF);
            __threadfence();
        }
    }

    // ---- Combiner: second of the two batch-final blocks. ----
    if (t == 0) {
        unsigned int old = atomicAdd(&g_done2, 1u);
        if (old == 1u) {
            float nmi_sum = g_nmi[0] + g_nmi[1];
            float mse = 0.f;
            #pragma unroll
            for (int i = 0; i < BATCH * 12; i++) {
                float d = pred[i] - tru[i];
                mse += d * d;
            }
            mse /= (float)(BATCH * 12);
            out[0] = mse - nmi_sum / (float)BATCH;
            // restore all scratch for the next call
            #pragma unroll
            for (int k = 0; k < 4; k++) {
                g_minmax[k * 2 + 0] = 0xFFFFFFFFu;
                g_minmax[k * 2 + 1] = 0u;
            }
            g_barB[0] = 0u;  g_barB[1] = 0u;
            g_doneB[0] = 0u; g_doneB[1] = 0u;
            g_nmi[0] = 0.f;  g_nmi[1] = 0.f;
            g_done2 = 0u;
            __threadfence();
        }
    }
}

extern "C" void kernel_launch(void* const* d_in, const int* in_sizes, int n_in,
                              void* d_out, int out_size) {
    const float* pred    = (const float*)d_in[0];
    const float* tru     = (const float*)d_in[1];
    const float* fixedp  = (const float*)d_in[2];
    const float* warpedp = (const float*)d_in[3];

    fusedK<<<NBLOCKS, HTHREADS>>>(fixedp, warpedp, pred, tru, (float*)d_out);
}

// round 15
// speedup vs baseline: 1.4047x; 1.4047x over previous
#include <cuda_runtime.h>

#define BINS     64
#define NB       (BINS * BINS)
#define BATCH    2
#define NELEM    (192 * 224 * 192)   /* 8,257,536 per batch */
#define N4       (NELEM / 4)
#define NHALF    (N4 / 2)
#define EPSF     1e-10f

#define NBLOCKS  444                 /* 3/SM x 148 SM: exactly one wave */
#define HTHREADS 512
#define BPB      (NBLOCKS / 2)       /* blocks per batch = 222 */

// Scratch. Self-restoring: everything reset by the combine block.
__device__ unsigned int g_hist[BATCH * NB];   // static-zeroed
__device__ unsigned int g_minmax[8] = {       // [c*2]=min-enc, [c*2+1]=max-enc
    0xFFFFFFFFu, 0u, 0xFFFFFFFFu, 0u,         // combo = arr*2 + b (arr0=fixed)
    0xFFFFFFFFu, 0u, 0xFFFFFFFFu, 0u
};
__device__ unsigned int g_barB[2]  = {0, 0};  // per-batch phase barrier
__device__ unsigned int g_doneB[2] = {0, 0};  // per-batch flush counter
__device__ unsigned int g_done2    = 0;       // combiner election
__device__ float        g_nmi[2]   = {0.f, 0.f};

__device__ __forceinline__ unsigned int fenc(float f) {
    unsigned int u = __float_as_uint(f);
    return (u & 0x80000000u) ? ~u : (u | 0x80000000u);
}
__device__ __forceinline__ float fdec(unsigned int e) {
    unsigned int u = (e & 0x80000000u) ? (e & 0x7fffffffu) : ~e;
    return __uint_as_float(u);
}
__device__ __forceinline__ int binof(float x, float s, float c) {
    return min(max(__float2int_rz(fmaf(x, s, c)), 0), BINS - 1);
}

// FINAL (R13 structure, best measured 41.2us):
// - persistent fused kernel, one wave (444 blocks x 512 thr, 3/SM: 48
//   warps/SM needed to saturate the smem-ATOMS pipe — R14 proved 32 is not
//   enough, R4/R6 proved more doesn't help)
// - phase 1 REVERSE min/max, phase 2 FORWARD histogram: alternating
//   traversal direction gives cross-phase AND cross-replay L2 reuse
// - all histogram atomics in SMEM (R5: L2-RED 7x worse at this density)
// - static partition (R10: work-stealing drains MLP; R12: asymmetric
//   splits starve the ATOMS pipe)
// - per-batch barriers + per-batch split finals + combiner (tail overlap)
__global__ void __launch_bounds__(HTHREADS, 3)
fusedK(const float* __restrict__ fixedp,
       const float* __restrict__ warpedp,
       const float* __restrict__ pred,
       const float* __restrict__ tru,
       float* __restrict__ out) {
    __shared__ unsigned int sh[NB];
    __shared__ float red[16];
    __shared__ float hmarg[2];
    __shared__ unsigned int s_last;
    int t   = threadIdx.x;
    int w   = t >> 5, l = t & 31;
    int bid = blockIdx.x;
    int b    = (bid >= BPB) ? 1 : 0;     // batch owned by this block
    int xbid = bid - b * BPB;            // 0..221 within batch

    // Zero private histogram early (hidden under phase-1 streaming).
    for (int i = t; i < NB; i += HTHREADS) sh[i] = 0u;

    const float4* f4 = (const float4*)(fixedp  + (size_t)b * NELEM);
    const float4* w4 = (const float4*)(warpedp + (size_t)b * NELEM);

    // ---- Phase 1: REVERSE min/max (tail L2-resident from previous
    // replay's forward phase 2; finishes at heads, feeding phase 2). ----
    {
        float fmn = 3.4e38f, fmx = -3.4e38f, wmn = 3.4e38f, wmx = -3.4e38f;
        for (int i = xbid * HTHREADS + t; i < N4; i += BPB * HTHREADS) {
            int j = (N4 - 1) - i;
            float4 f = f4[j];
            float4 wv = w4[j];
            fmn = fminf(fmn, fminf(fminf(f.x, f.y), fminf(f.z, f.w)));
            fmx = fmaxf(fmx, fmaxf(fmaxf(f.x, f.y), fmaxf(f.z, f.w)));
            wmn = fminf(wmn, fminf(fminf(wv.x, wv.y), fminf(wv.z, wv.w)));
            wmx = fmaxf(wmx, fmaxf(fmaxf(wv.x, wv.y), fmaxf(wv.z, wv.w)));
        }
        #pragma unroll
        for (int o = 16; o; o >>= 1) {
            fmn = fminf(fmn, __shfl_down_sync(0xFFFFFFFFu, fmn, o));
            fmx = fmaxf(fmx, __shfl_down_sync(0xFFFFFFFFu, fmx, o));
            wmn = fminf(wmn, __shfl_down_sync(0xFFFFFFFFu, wmn, o));
            wmx = fmaxf(wmx, __shfl_down_sync(0xFFFFFFFFu, wmx, o));
        }
        __shared__ float s0[16], s1[16], s2[16], s3[16];
        if (l == 0) { s0[w] = fmn; s1[w] = fmx; s2[w] = wmn; s3[w] = wmx; }
        __syncthreads();
        if (t == 0) {
            float a = s0[0], bb = s1[0], c = s2[0], d = s3[0];
            #pragma unroll
            for (int k = 1; k < 16; k++) {
                a = fminf(a, s0[k]); bb = fmaxf(bb, s1[k]);
                c = fminf(c, s2[k]); d = fmaxf(d, s3[k]);
            }
            atomicMin(&g_minmax[(0 * 2 + b) * 2 + 0], fenc(a));
            atomicMax(&g_minmax[(0 * 2 + b) * 2 + 1], fenc(bb));
            atomicMin(&g_minmax[(1 * 2 + b) * 2 + 0], fenc(c));
            atomicMax(&g_minmax[(1 * 2 + b) * 2 + 1], fenc(d));
            __threadfence();
            atomicAdd(&g_barB[b], 1u);
        }
    }

    // ---- Per-batch barrier: wait only for this batch's 222 blocks. ----
    if (t == 0) {
        while (atomicAdd(&g_barB[b], 0u) < BPB) __nanosleep(64);
    }
    __syncthreads();
    __threadfence();   // acquire: order g_minmax reads after the spin

    // ---- Phase 2: FORWARD histogram, two-stream for MLP. ----
    float fmn = fdec(g_minmax[(0 * 2 + b) * 2 + 0]);
    float fmx = fdec(g_minmax[(0 * 2 + b) * 2 + 1]);
    float wmn = fdec(g_minmax[(1 * 2 + b) * 2 + 0]);
    float wmx = fdec(g_minmax[(1 * 2 + b) * 2 + 1]);
    float fs = (float)(BINS - 1) / (fmx - fmn + EPSF);
    float ws = (float)(BINS - 1) / (wmx - wmn + EPSF);
    float fc = -fmn * fs;
    float wc = -wmn * ws;

    for (int i = xbid * HTHREADS + t; i < NHALF; i += BPB * HTHREADS) {
        float4 f0 = f4[i];
        float4 w0 = w4[i];
        float4 f1 = f4[i + NHALF];
        float4 w1 = w4[i + NHALF];
        atomicAdd(&sh[binof(f0.x, fs, fc) * BINS + binof(w0.x, ws, wc)], 1u);
        atomicAdd(&sh[binof(f0.y, fs, fc) * BINS + binof(w0.y, ws, wc)], 1u);
        atomicAdd(&sh[binof(f0.z, fs, fc) * BINS + binof(w0.z, ws, wc)], 1u);
        atomicAdd(&sh[binof(f0.w, fs, fc) * BINS + binof(w0.w, ws, wc)], 1u);
        atomicAdd(&sh[binof(f1.x, fs, fc) * BINS + binof(w1.x, ws, wc)], 1u);
        atomicAdd(&sh[binof(f1.y, fs, fc) * BINS + binof(w1.y, ws, wc)], 1u);
        atomicAdd(&sh[binof(f1.z, fs, fc) * BINS + binof(w1.z, ws, wc)], 1u);
        atomicAdd(&sh[binof(f1.w, fs, fc) * BINS + binof(w1.w, ws, wc)], 1u);
    }
    __syncthreads();

    // Flush as packed u64 (low half can't carry into high: counts << 2^32).
    unsigned long long* gh64 = (unsigned long long*)(g_hist + b * NB);
    const unsigned long long* sh64 = (const unsigned long long*)sh;
    for (int i = t; i < NB / 2; i += HTHREADS) {
        unsigned long long v = sh64[i];
        if (v) atomicAdd(&gh64[i], v);
    }
    __threadfence();
    __syncthreads();

    // ---- Per-batch last-block does this batch's entropy/NMI. ----
    if (t == 0) {
        unsigned int old = atomicAdd(&g_doneB[b], 1u);
        s_last = (old == BPB - 1) ? 1u : 0u;
    }
    __syncthreads();
    if (!s_last) return;

    __threadfence();
    float* shf = (float*)sh;
    const float invN = 1.0f / ((float)NELEM + EPSF);
    {
        unsigned int* gh = g_hist + b * NB;
        if (t < 2) hmarg[t] = 0.f;

        float hj = 0.f;
        #pragma unroll
        for (int k = 0; k < NB / HTHREADS; k++) {
            int i = t + k * HTHREADS;
            float c = (float)__ldcg(&gh[i]);
            gh[i] = 0u;              // self-restore
            shf[i] = c;
            float p = c * invN;
            hj -= p * __logf(p + EPSF);
        }
        #pragma unroll
        for (int o = 16; o; o >>= 1) hj += __shfl_down_sync(0xFFFFFFFFu, hj, o);
        if (l == 0) red[w] = hj;
        __syncthreads();

        float hterm = 0.f;
        if (t < 64) {
            float rs = 0.f;
            #pragma unroll
            for (int j = 0; j < BINS; j++) rs += shf[t * BINS + ((j + t) & 63)];
            float p = rs * invN;
            hterm = -p * __logf(p + EPSF);
        } else if (t < 128) {
            int c = t - 64;
            float cs = 0.f;
            #pragma unroll
            for (int j = 0; j < BINS; j++) cs += shf[j * BINS + c];
            float p = cs * invN;
            hterm = -p * __logf(p + EPSF);
        }
        #pragma unroll
        for (int o = 16; o; o >>= 1)
            hterm += __shfl_down_sync(0xFFFFFFFFu, hterm, o);
        if (l == 0 && w < 4) atomicAdd(&hmarg[w >> 1], hterm);
        __syncthreads();

        if (t == 0) {
            float h_j = 0.f;
            #pragma unroll
            for (int k = 0; k < 16; k++) h_j += red[k];
            float h_f = hmarg[0], h_w = hmarg[1];
            g_nmi[b] = 2.f * (h_f + h_w - h_j) / (h_f + h_w + EPSF);
            __threadfence();
        }
    }

    // ---- Combiner: second of the two batch-final blocks. ----
    if (t == 0) {
        unsigned int old = atomicAdd(&g_done2, 1u);
        if (old == 1u) {
            float nmi_sum = g_nmi[0] + g_nmi[1];
            float mse = 0.f;
            #pragma unroll
            for (int i = 0; i < BATCH * 12; i++) {
                float d = pred[i] - tru[i];
                mse += d * d;
            }
            mse /= (float)(BATCH * 12);
            out[0] = mse - nmi_sum / (float)BATCH;
            // restore all scratch for the next call
            #pragma unroll
            for (int k = 0; k < 4; k++) {
                g_minmax[k * 2 + 0] = 0xFFFFFFFFu;
                g_minmax[k * 2 + 1] = 0u;
            }
            g_barB[0] = 0u;  g_barB[1] = 0u;
            g_doneB[0] = 0u; g_doneB[1] = 0u;
            g_nmi[0] = 0.f;  g_nmi[1] = 0.f;
            g_done2 = 0u;
            __threadfence();
        }
    }
}

extern "C" void kernel_launch(void* const* d_in, const int* in_sizes, int n_in,
                              void* d_out, int out_size) {
    const float* pred    = (const float*)d_in[0];
    const float* tru     = (const float*)d_in[1];
    const float* fixedp  = (const float*)d_in[2];
    const float* warpedp = (const float*)d_in[3];

    fusedK<<<NBLOCKS, HTHREADS>>>(fixedp, warpedp, pred, tru, (float*)d_out);
}